// round 6
// baseline (speedup 1.0000x reference)
#include <cuda_runtime.h>
#include <cuda_bf16.h>
#include <math.h>

#define BB 2
#define LL 2048
#define SS 2048
#define HH 16
#define EE 64
#define TQ 128
#define TK 64
#define PITCH 144  // smem row pitch: 64 bf16 (128B) + 16B pad

#define NELEM (BB * HH * LL * EE)

__device__ __align__(16) __nv_bfloat16 gQh[NELEM], gQl[NELEM];
__device__ __align__(16) __nv_bfloat16 gKh[NELEM], gKl[NELEM];
__device__ __align__(16) __nv_bfloat16 gVh[NELEM], gVl[NELEM];

// ---------------- helpers ----------------
__device__ __forceinline__ unsigned smem_u32(const void* p) {
    unsigned a;
    asm("{ .reg .u64 t; cvta.to.shared.u64 t, %1; cvt.u32.u64 %0, t; }"
        : "=r"(a) : "l"(p));
    return a;
}
#define CP16(dst, src) \
    asm volatile("cp.async.cg.shared.global [%0], [%1], 16;" :: "r"(dst), "l"(src))
#define CP_COMMIT() asm volatile("cp.async.commit_group;" ::: "memory")
#define CP_WAIT0()  asm volatile("cp.async.wait_group 0;" ::: "memory")

__device__ __forceinline__ void ldsm4(unsigned r[4], unsigned addr) {
    asm volatile("ldmatrix.sync.aligned.m8n8.x4.shared.b16 {%0,%1,%2,%3}, [%4];"
                 : "=r"(r[0]), "=r"(r[1]), "=r"(r[2]), "=r"(r[3]) : "r"(addr));
}
__device__ __forceinline__ void ldsm4t(unsigned r[4], unsigned addr) {
    asm volatile("ldmatrix.sync.aligned.m8n8.x4.trans.shared.b16 {%0,%1,%2,%3}, [%4];"
                 : "=r"(r[0]), "=r"(r[1]), "=r"(r[2]), "=r"(r[3]) : "r"(addr));
}
__device__ __forceinline__ void mma16816(float* c, const unsigned a[4],
                                         unsigned b0, unsigned b1) {
    asm volatile(
        "mma.sync.aligned.m16n8k16.row.col.f32.bf16.bf16.f32 "
        "{%0,%1,%2,%3}, {%4,%5,%6,%7}, {%8,%9}, {%0,%1,%2,%3};"
        : "+f"(c[0]), "+f"(c[1]), "+f"(c[2]), "+f"(c[3])
        : "r"(a[0]), "r"(a[1]), "r"(a[2]), "r"(a[3]), "r"(b0), "r"(b1));
}
__device__ __forceinline__ unsigned pack2(float lo, float hi) {
    __nv_bfloat162 p = __floats2bfloat162_rn(lo, hi);
    return *reinterpret_cast<unsigned*>(&p);
}

// ---------------------------------------------------------------------------
// Prep: fp32 [b,s,h,e] -> bf16 hi/lo [b,h,s,e]; Q scaled by exactly 0.125.
// ---------------------------------------------------------------------------
__global__ __launch_bounds__(256)
void prep(const float* __restrict__ Q, const float* __restrict__ K,
          const float* __restrict__ V) {
    const unsigned per = NELEM / 4;
    unsigned idx = blockIdx.x * 256u + threadIdx.x;
    if (idx >= 3u * per) return;
    const int t = idx / per;
    const unsigned c = idx % per;

    const unsigned e4 = c & 15;
    const unsigned r  = c >> 4;
    const unsigned h  = r & (HH - 1);
    const unsigned bs = r >> 4;
    const unsigned s  = bs & (LL - 1);
    const unsigned b  = bs >> 11;

    const float* src = (t == 0) ? Q : (t == 1) ? K : V;
    float4 v = *(const float4*)(src + (size_t)c * 4);
    if (t == 0) { v.x *= 0.125f; v.y *= 0.125f; v.z *= 0.125f; v.w *= 0.125f; }

    float h0 = __bfloat162float(__float2bfloat16(v.x));
    float h1 = __bfloat162float(__float2bfloat16(v.y));
    float h2 = __bfloat162float(__float2bfloat16(v.z));
    float h3 = __bfloat162float(__float2bfloat16(v.w));

    __nv_bfloat16* oh = (t == 0) ? gQh : (t == 1) ? gKh : gVh;
    __nv_bfloat16* ol = (t == 0) ? gQl : (t == 1) ? gKl : gVl;
    const size_t o = (((size_t)(b * HH + h) * LL + s) * EE) + e4 * 4;
    *(uint2*)(oh + o) = make_uint2(pack2(h0, h1), pack2(h2, h3));
    *(uint2*)(ol + o) = make_uint2(pack2(v.x - h0, v.y - h1), pack2(v.z - h2, v.w - h3));
}

// ---------------------------------------------------------------------------
// Fused attention, TQ=128, 8 warps. Sweep 1: exact row sums. Sweep 2:
// recompute S (bitwise identical), write NORMALIZED A and O directly.
// ---------------------------------------------------------------------------
__global__ __launch_bounds__(256, 2)
void attn_tc(float* __restrict__ Aout, float* __restrict__ Vout) {
    extern __shared__ char sm[];
    const unsigned uS  = smem_u32(sm);
    const unsigned uQh = uS, uQl = uS + 18432;          // 128 rows x PITCH each
    const unsigned uKB = uS + 36864;                     // 2 bufs x (hi|lo) 18432
    const unsigned uVB = uS + 73728;                     // 2 bufs x (hi|lo) 18432

    const int tid  = threadIdx.x;
    const int lane = tid & 31;
    const int w    = tid >> 5;        // 0..7
    const int g    = lane >> 2;
    const int tig  = lane & 3;

    const int bh = blockIdx.y;
    const int b  = bh / HH, h = bh % HH;
    const int qt = (int)gridDim.x - 1 - (int)blockIdx.x;  // heavy tiles first
    const int q0 = qt * TQ;

    const size_t qbase  = ((size_t)bh * LL + q0) * EE;
    const size_t kvbase = (size_t)bh * LL * EE;
    const int nkt = 2 * qt + 2;       // 64-row k-tiles in causal range

    // ---- issue Q tile (128 rows hi+lo = 2048 x 16B) + K tile 0 ----
    for (int c = tid; c < 2048; c += 256) {
        const int which = c >> 10, i = (c >> 3) & 127, ch = c & 7;
        const __nv_bfloat16* src = (which ? gQl : gQh) + qbase + (size_t)i * EE + ch * 8;
        CP16((which ? uQl : uQh) + i * PITCH + ch * 16, src);
    }
    for (int c = tid; c < 1024; c += 256) {
        const int which = c >> 9, i = (c >> 3) & 63, ch = c & 7;
        const __nv_bfloat16* src = (which ? gKl : gKh) + kvbase + (size_t)i * EE + ch * 8;
        CP16(uKB + which * 9216 + i * PITCH + ch * 16, src);
    }
    CP_COMMIT();

    const int lr  = (lane & 7) + ((lane >> 3) & 1) * 8;
    const int lco = (lane >> 4) * 8;
    const unsigned qrow = (unsigned)((w * 16 + lr) * PITCH + lco * 2);
    const unsigned krow = (unsigned)(lr * PITCH + lco * 2);

    const int gi0 = q0 + w * 16 + g;
    const int gi1 = gi0 + 8;

    float rsum0 = 0.0f, rsum1 = 0.0f;

    // ================= sweep 1: row sums only =================
    for (int kt = 0; kt < nkt; ++kt) {
        CP_WAIT0();
        __syncthreads();
        if (kt + 1 < nkt) {  // prefetch K[kt+1]
            const unsigned uN = uKB + ((kt + 1) & 1) * 18432u;
            const size_t rb = kvbase + (size_t)(kt + 1) * TK * EE;
            for (int c = tid; c < 1024; c += 256) {
                const int which = c >> 9, i = (c >> 3) & 63, ch = c & 7;
                const __nv_bfloat16* src = (which ? gKl : gKh) + rb + (size_t)i * EE + ch * 8;
                CP16(uN + which * 9216 + i * PITCH + ch * 16, src);
            }
            CP_COMMIT();
        }
        const unsigned uKh = uKB + (kt & 1) * 18432u, uKl = uKh + 9216;

        float s[8][4];
#pragma unroll
        for (int nb = 0; nb < 8; ++nb)
#pragma unroll
            for (int c = 0; c < 4; ++c) s[nb][c] = 0.0f;
#pragma unroll
        for (int ks = 0; ks < 4; ++ks) {
            unsigned qh[4], ql[4];
            ldsm4(qh, uQh + qrow + ks * 32);
            ldsm4(ql, uQl + qrow + ks * 32);
#pragma unroll
            for (int jg = 0; jg < 4; ++jg) {
                unsigned kh[4], kl[4];
                const unsigned ko = jg * 16 * PITCH + krow + ks * 32;
                ldsm4(kh, uKh + ko);
                ldsm4(kl, uKl + ko);
                mma16816(s[2 * jg],     qh, kh[0], kh[2]);
                mma16816(s[2 * jg],     qh, kl[0], kl[2]);
                mma16816(s[2 * jg],     ql, kh[0], kh[2]);
                mma16816(s[2 * jg + 1], qh, kh[1], kh[3]);
                mma16816(s[2 * jg + 1], qh, kl[1], kl[3]);
                mma16816(s[2 * jg + 1], ql, kh[1], kh[3]);
            }
        }
        const int k0 = kt * TK;
        const bool anymask = (k0 + TK > gi0);  // tile reaches past some row
#pragma unroll
        for (int nb = 0; nb < 8; ++nb) {
            const int cj = k0 + nb * 8 + 2 * tig;
            float e0 = __expf(s[nb][0]);
            float e1 = __expf(s[nb][1]);
            float e2 = __expf(s[nb][2]);
            float e3 = __expf(s[nb][3]);
            if (anymask) {
                if (cj     > gi0) e0 = 0.0f;
                if (cj + 1 > gi0) e1 = 0.0f;
                if (cj     > gi1) e2 = 0.0f;
                if (cj + 1 > gi1) e3 = 0.0f;
            }
            rsum0 += e0 + e1;
            rsum1 += e2 + e3;
        }
    }

    rsum0 += __shfl_xor_sync(0xffffffffu, rsum0, 1);
    rsum0 += __shfl_xor_sync(0xffffffffu, rsum0, 2);
    rsum1 += __shfl_xor_sync(0xffffffffu, rsum1, 1);
    rsum1 += __shfl_xor_sync(0xffffffffu, rsum1, 2);
    const float inv0 = 1.0f / rsum0, inv1 = 1.0f / rsum1;

    // ---- issue K0+V0 for sweep 2, overlap zero-fill with loads ----
    __syncthreads();
    for (int c = tid; c < 2048; c += 256) {
        const int arr = c >> 9, i = (c >> 3) & 63, ch = c & 7;
        const __nv_bfloat16* gsrc = (arr == 0) ? gKh : (arr == 1) ? gKl
                                  : (arr == 2) ? gVh : gVl;
        const unsigned dst = (arr < 2 ? uKB + (arr & 1) * 9216u
                                      : uVB + (arr & 1) * 9216u);
        CP16(dst + i * PITCH + ch * 16, gsrc + kvbase + (size_t)i * EE + ch * 8);
    }
    CP_COMMIT();

    if (Aout) {  // zero the strictly-upper rectangle of this q-strip
        const int c0 = q0 + TQ;
        const int w4 = (SS - c0) >> 2;
        if (w4 > 0) {
            const float4 z = make_float4(0.f, 0.f, 0.f, 0.f);
            float* Abase = Aout + ((size_t)bh * LL + q0) * SS + c0;
            for (int i = tid; i < TQ * w4; i += 256) {
                const int r = i / w4;
                const int c = i - r * w4;
                __stcs((float4*)(Abase + (size_t)r * SS + 4 * c), z);
            }
        }
    }

    float o[8][4];
#pragma unroll
    for (int nb = 0; nb < 8; ++nb)
#pragma unroll
        for (int c = 0; c < 4; ++c) o[nb][c] = 0.0f;

    // ================= sweep 2: normalized A + O =================
    for (int kt = 0; kt < nkt; ++kt) {
        const int k0 = kt * TK;
        CP_WAIT0();
        __syncthreads();
        if (kt + 1 < nkt) {  // prefetch K/V[kt+1]
            const unsigned nb1 = (kt + 1) & 1;
            const size_t rb = kvbase + (size_t)(kt + 1) * TK * EE;
            for (int c = tid; c < 2048; c += 256) {
                const int arr = c >> 9, i = (c >> 3) & 63, ch = c & 7;
                const __nv_bfloat16* gsrc = (arr == 0) ? gKh : (arr == 1) ? gKl
                                          : (arr == 2) ? gVh : gVl;
                const unsigned base = (arr < 2) ? uKB + nb1 * 18432u + (arr & 1) * 9216u
                                                : uVB + nb1 * 18432u + (arr & 1) * 9216u;
                CP16(base + i * PITCH + ch * 16, gsrc + rb + (size_t)i * EE + ch * 8);
            }
            CP_COMMIT();
        }
        const unsigned uKh = uKB + (kt & 1) * 18432u, uKl = uKh + 9216;
        const unsigned uVh = uVB + (kt & 1) * 18432u, uVl = uVh + 9216;

        float s[8][4];
#pragma unroll
        for (int nb = 0; nb < 8; ++nb)
#pragma unroll
            for (int c = 0; c < 4; ++c) s[nb][c] = 0.0f;
#pragma unroll
        for (int ks = 0; ks < 4; ++ks) {
            unsigned qh[4], ql[4];
            ldsm4(qh, uQh + qrow + ks * 32);
            ldsm4(ql, uQl + qrow + ks * 32);
#pragma unroll
            for (int jg = 0; jg < 4; ++jg) {
                unsigned kh[4], kl[4];
                const unsigned ko = jg * 16 * PITCH + krow + ks * 32;
                ldsm4(kh, uKh + ko);
                ldsm4(kl, uKl + ko);
                mma16816(s[2 * jg],     qh, kh[0], kh[2]);
                mma16816(s[2 * jg],     qh, kl[0], kl[2]);
                mma16816(s[2 * jg],     ql, kh[0], kh[2]);
                mma16816(s[2 * jg + 1], qh, kh[1], kh[3]);
                mma16816(s[2 * jg + 1], qh, kl[1], kl[3]);
                mma16816(s[2 * jg + 1], ql, kh[1], kh[3]);
            }
        }

        const bool anymask = (k0 + TK > gi0);
        float* A0 = Aout ? (Aout + ((size_t)bh * LL + gi0) * SS + k0) : (float*)0;
        float* A1 = Aout ? (Aout + ((size_t)bh * LL + gi1) * SS + k0) : (float*)0;

        // per-ks: epilogue for nb pair, then PV MMAs (keeps s[] lifetime short)
#pragma unroll
        for (int ks = 0; ks < 4; ++ks) {
            unsigned ah[4], al[4];
#pragma unroll
            for (int half = 0; half < 2; ++half) {
                const int nb = 2 * ks + half;
                const int cj = k0 + nb * 8 + 2 * tig;
                float e0 = __expf(s[nb][0]);
                float e1 = __expf(s[nb][1]);
                float e2 = __expf(s[nb][2]);
                float e3 = __expf(s[nb][3]);
                if (anymask) {
                    if (cj     > gi0) e0 = 0.0f;
                    if (cj + 1 > gi0) e1 = 0.0f;
                    if (cj     > gi1) e2 = 0.0f;
                    if (cj + 1 > gi1) e3 = 0.0f;
                }
                e0 *= inv0; e1 *= inv0; e2 *= inv1; e3 *= inv1;
                if (A0) {
                    __stcs((float2*)(A0 + nb * 8 + 2 * tig), make_float2(e0, e1));
                    __stcs((float2*)(A1 + nb * 8 + 2 * tig), make_float2(e2, e3));
                }
                float h0 = __bfloat162float(__float2bfloat16(e0));
                float h1 = __bfloat162float(__float2bfloat16(e1));
                float h2 = __bfloat162float(__float2bfloat16(e2));
                float h3 = __bfloat162float(__float2bfloat16(e3));
                ah[2 * half]     = pack2(h0, h1);
                ah[2 * half + 1] = pack2(h2, h3);
                al[2 * half]     = pack2(e0 - h0, e1 - h1);
                al[2 * half + 1] = pack2(e2 - h2, e3 - h3);
            }
#pragma unroll
            for (int dg = 0; dg < 4; ++dg) {
                unsigned vh[4], vl[4];
                const unsigned vo = ks * 16 * PITCH + krow + dg * 32;
                ldsm4t(vh, uVh + vo);
                ldsm4t(vl, uVl + vo);
                mma16816(o[2 * dg],     ah, vh[0], vh[1]);
                mma16816(o[2 * dg],     ah, vl[0], vl[1]);
                mma16816(o[2 * dg],     al, vh[0], vh[1]);
                mma16816(o[2 * dg + 1], ah, vh[2], vh[3]);
                mma16816(o[2 * dg + 1], ah, vl[2], vl[3]);
                mma16816(o[2 * dg + 1], al, vh[2], vh[3]);
            }
        }
    }

    if (Vout) {
        float* O0 = Vout + (((size_t)(b * LL + gi0) * HH + h) * EE);
        float* O1 = Vout + (((size_t)(b * LL + gi1) * HH + h) * EE);
#pragma unroll
        for (int nb = 0; nb < 8; ++nb) {
            *(float2*)(O0 + nb * 8 + 2 * tig) = make_float2(o[nb][0], o[nb][1]);
            *(float2*)(O1 + nb * 8 + 2 * tig) = make_float2(o[nb][2], o[nb][3]);
        }
    }
}

// ---------------------------------------------------------------------------
extern "C" void kernel_launch(void* const* d_in, const int* in_sizes, int n_in,
                              void* d_out, int out_size) {
    const float* Q = (const float*)d_in[0];
    const float* K = (const float*)d_in[1];
    const float* V = (const float*)d_in[2];

    const int V_SIZE = BB * LL * HH * EE;
    const int A_SIZE = (int)((size_t)BB * HH * LL * SS);

    float* out  = (float*)d_out;
    float* Vout = 0;
    float* Aout = 0;
    if (out_size >= V_SIZE + A_SIZE) { Vout = out; Aout = out + V_SIZE; }
    else if (out_size == A_SIZE)     { Aout = out; }
    else                             { Vout = out; }

    const unsigned prep_total = 3u * (NELEM / 4);
    prep<<<(prep_total + 255u) / 256u, 256>>>(Q, K, V);

    const int smem = 110592;
    cudaFuncSetAttribute(attn_tc, cudaFuncAttributeMaxDynamicSharedMemorySize, smem);
    dim3 grid1(LL / TQ, BB * HH);
    attn_tc<<<grid1, 256, smem>>>(Aout, Vout);
}

// round 7
// speedup vs baseline: 1.7973x; 1.7973x over previous
#include <cuda_runtime.h>
#include <cuda_fp16.h>
#include <math.h>

#define BB 2
#define LL 2048
#define SS 2048
#define HH 16
#define EE 64
#define TQ 128
#define TK 64
#define PITCH 144  // smem row pitch: 64 fp16 (128B) + 16B pad

#define NELEM (BB * HH * LL * EE)

__device__ __align__(16) __half gQ[NELEM];
__device__ __align__(16) __half gK[NELEM];
__device__ __align__(16) __half gV[NELEM];

// ---------------- helpers ----------------
__device__ __forceinline__ unsigned smem_u32(const void* p) {
    unsigned a;
    asm("{ .reg .u64 t; cvta.to.shared.u64 t, %1; cvt.u32.u64 %0, t; }"
        : "=r"(a) : "l"(p));
    return a;
}
#define CP16(dst, src) \
    asm volatile("cp.async.cg.shared.global [%0], [%1], 16;" :: "r"(dst), "l"(src))
#define CP_COMMIT() asm volatile("cp.async.commit_group;" ::: "memory")
#define CP_WAIT0()  asm volatile("cp.async.wait_group 0;" ::: "memory")

__device__ __forceinline__ void ldsm4(unsigned r[4], unsigned addr) {
    asm volatile("ldmatrix.sync.aligned.m8n8.x4.shared.b16 {%0,%1,%2,%3}, [%4];"
                 : "=r"(r[0]), "=r"(r[1]), "=r"(r[2]), "=r"(r[3]) : "r"(addr));
}
__device__ __forceinline__ void ldsm4t(unsigned r[4], unsigned addr) {
    asm volatile("ldmatrix.sync.aligned.m8n8.x4.trans.shared.b16 {%0,%1,%2,%3}, [%4];"
                 : "=r"(r[0]), "=r"(r[1]), "=r"(r[2]), "=r"(r[3]) : "r"(addr));
}
__device__ __forceinline__ void mma16816(float* c, const unsigned a[4],
                                         unsigned b0, unsigned b1) {
    asm volatile(
        "mma.sync.aligned.m16n8k16.row.col.f32.f16.f16.f32 "
        "{%0,%1,%2,%3}, {%4,%5,%6,%7}, {%8,%9}, {%0,%1,%2,%3};"
        : "+f"(c[0]), "+f"(c[1]), "+f"(c[2]), "+f"(c[3])
        : "r"(a[0]), "r"(a[1]), "r"(a[2]), "r"(a[3]), "r"(b0), "r"(b1));
}
__device__ __forceinline__ unsigned pack2h(float lo, float hi) {
    __half2 p = __floats2half2_rn(lo, hi);
    return *reinterpret_cast<unsigned*>(&p);
}

// ---------------------------------------------------------------------------
// Prep: fp32 [b,s,h,e] -> fp16 [b,h,s,e]; Q scaled by 0.125*log2(e) so the
// attention epilogue uses exp2 directly (1 MUFU, no multiply).
// ---------------------------------------------------------------------------
__global__ __launch_bounds__(256)
void prep(const float* __restrict__ Q, const float* __restrict__ K,
          const float* __restrict__ V) {
    const unsigned per = NELEM / 4;
    unsigned idx = blockIdx.x * 256u + threadIdx.x;
    if (idx >= 3u * per) return;
    const int t = idx / per;
    const unsigned c = idx % per;

    const unsigned e4 = c & 15;
    const unsigned r  = c >> 4;
    const unsigned h  = r & (HH - 1);
    const unsigned bs = r >> 4;
    const unsigned s  = bs & (LL - 1);
    const unsigned b  = bs >> 11;

    const float* src = (t == 0) ? Q : (t == 1) ? K : V;
    float4 v = *(const float4*)(src + (size_t)c * 4);
    if (t == 0) {
        const float sc = 0.18033688011112042f;  // 0.125 * log2(e)
        v.x *= sc; v.y *= sc; v.z *= sc; v.w *= sc;
    }
    __half* oh = (t == 0) ? gQ : (t == 1) ? gK : gV;
    const size_t o = (((size_t)(b * HH + h) * LL + s) * EE) + e4 * 4;
    *(uint2*)(oh + o) = make_uint2(pack2h(v.x, v.y), pack2h(v.z, v.w));
}

// ---------------------------------------------------------------------------
// Fused attention, fp16 MMAs, TQ=128. Sweep 1: exact row sums (exp2 of S).
// Sweep 2: recompute identical S, write NORMALIZED A and O directly.
// ---------------------------------------------------------------------------
__global__ __launch_bounds__(256, 2)
void attn_tc(float* __restrict__ Aout, float* __restrict__ Vout) {
    extern __shared__ char sm[];
    const unsigned uS  = smem_u32(sm);
    const unsigned uQ  = uS;                 // 128 rows x PITCH = 18432
    const unsigned uKB = uS + 18432;         // 2 bufs x 9216
    const unsigned uVB = uS + 36864;         // 2 bufs x 9216

    const int tid  = threadIdx.x;
    const int lane = tid & 31;
    const int w    = tid >> 5;        // 0..7
    const int g    = lane >> 2;
    const int tig  = lane & 3;

    const int bh = blockIdx.y;
    const int b  = bh / HH, h = bh % HH;
    const int qt = (int)gridDim.x - 1 - (int)blockIdx.x;  // heavy tiles first
    const int q0 = qt * TQ;

    const size_t qbase  = ((size_t)bh * LL + q0) * EE;
    const size_t kvbase = (size_t)bh * LL * EE;
    const int nkt = 2 * qt + 2;

    // ---- issue Q tile (1024 x 16B) + K tile 0 (512 x 16B) ----
    for (int c = tid; c < 1024; c += 256) {
        const int i = c >> 3, ch = c & 7;
        CP16(uQ + i * PITCH + ch * 16, gQ + qbase + (size_t)i * EE + ch * 8);
    }
    for (int c = tid; c < 512; c += 256) {
        const int i = c >> 3, ch = c & 7;
        CP16(uKB + i * PITCH + ch * 16, gK + kvbase + (size_t)i * EE + ch * 8);
    }
    CP_COMMIT();

    const int lr  = (lane & 7) + ((lane >> 3) & 1) * 8;
    const int lco = (lane >> 4) * 8;
    const unsigned qrow = (unsigned)((w * 16 + lr) * PITCH + lco * 2);
    const unsigned krow = (unsigned)(lr * PITCH + lco * 2);

    const int gi0 = q0 + w * 16 + g;
    const int gi1 = gi0 + 8;

    float rsum0 = 0.0f, rsum1 = 0.0f;

    // ================= sweep 1: row sums only =================
    for (int kt = 0; kt < nkt; ++kt) {
        CP_WAIT0();
        __syncthreads();
        if (kt + 1 < nkt) {  // prefetch K[kt+1]
            const unsigned uN = uKB + ((kt + 1) & 1) * 9216u;
            const size_t rb = kvbase + (size_t)(kt + 1) * TK * EE;
            for (int c = tid; c < 512; c += 256) {
                const int i = c >> 3, ch = c & 7;
                CP16(uN + i * PITCH + ch * 16, gK + rb + (size_t)i * EE + ch * 8);
            }
            CP_COMMIT();
        }
        const unsigned uK = uKB + (kt & 1) * 9216u;

        float s[8][4];
#pragma unroll
        for (int nb = 0; nb < 8; ++nb)
#pragma unroll
            for (int c = 0; c < 4; ++c) s[nb][c] = 0.0f;
#pragma unroll
        for (int ks = 0; ks < 4; ++ks) {
            unsigned qf[4];
            ldsm4(qf, uQ + qrow + ks * 32);
#pragma unroll
            for (int jg = 0; jg < 4; ++jg) {
                unsigned kf[4];
                ldsm4(kf, uK + jg * 16 * PITCH + krow + ks * 32);
                mma16816(s[2 * jg],     qf, kf[0], kf[2]);
                mma16816(s[2 * jg + 1], qf, kf[1], kf[3]);
            }
        }
        const int k0 = kt * TK;
        const bool anymask = (k0 + TK > gi0);
#pragma unroll
        for (int nb = 0; nb < 8; ++nb) {
            const int cj = k0 + nb * 8 + 2 * tig;
            float e0 = exp2f(s[nb][0]);
            float e1 = exp2f(s[nb][1]);
            float e2 = exp2f(s[nb][2]);
            float e3 = exp2f(s[nb][3]);
            if (anymask) {
                if (cj     > gi0) e0 = 0.0f;
                if (cj + 1 > gi0) e1 = 0.0f;
                if (cj     > gi1) e2 = 0.0f;
                if (cj + 1 > gi1) e3 = 0.0f;
            }
            rsum0 += e0 + e1;
            rsum1 += e2 + e3;
        }
    }

    rsum0 += __shfl_xor_sync(0xffffffffu, rsum0, 1);
    rsum0 += __shfl_xor_sync(0xffffffffu, rsum0, 2);
    rsum1 += __shfl_xor_sync(0xffffffffu, rsum1, 1);
    rsum1 += __shfl_xor_sync(0xffffffffu, rsum1, 2);
    const float inv0 = 1.0f / rsum0, inv1 = 1.0f / rsum1;

    // ---- issue K0+V0 for sweep 2, overlap zero-fill with loads ----
    __syncthreads();
    for (int c = tid; c < 1024; c += 256) {
        const int arr = c >> 9, i = (c >> 3) & 63, ch = c & 7;
        const __half* gsrc = arr ? gV : gK;
        const unsigned dst = arr ? uVB : uKB;
        CP16(dst + i * PITCH + ch * 16, gsrc + kvbase + (size_t)i * EE + ch * 8);
    }
    CP_COMMIT();

    if (Aout) {  // zero the strictly-upper rectangle of this q-strip
        const int c0 = q0 + TQ;
        const int w4 = (SS - c0) >> 2;
        if (w4 > 0) {
            const float4 z = make_float4(0.f, 0.f, 0.f, 0.f);
            float* Abase = Aout + ((size_t)bh * LL + q0) * SS + c0;
            for (int i = tid; i < TQ * w4; i += 256) {
                const int r = i / w4;
                const int c = i - r * w4;
                __stcs((float4*)(Abase + (size_t)r * SS + 4 * c), z);
            }
        }
    }

    float o[8][4];
#pragma unroll
    for (int nb = 0; nb < 8; ++nb)
#pragma unroll
        for (int c = 0; c < 4; ++c) o[nb][c] = 0.0f;

    // ================= sweep 2: normalized A + O =================
    for (int kt = 0; kt < nkt; ++kt) {
        const int k0 = kt * TK;
        CP_WAIT0();
        __syncthreads();
        if (kt + 1 < nkt) {  // prefetch K/V[kt+1]
            const unsigned nb1 = (kt + 1) & 1;
            const size_t rb = kvbase + (size_t)(kt + 1) * TK * EE;
            for (int c = tid; c < 1024; c += 256) {
                const int arr = c >> 9, i = (c >> 3) & 63, ch = c & 7;
                const __half* gsrc = arr ? gV : gK;
                const unsigned base = (arr ? uVB : uKB) + nb1 * 9216u;
                CP16(base + i * PITCH + ch * 16, gsrc + rb + (size_t)i * EE + ch * 8);
            }
            CP_COMMIT();
        }
        const unsigned uK = uKB + (kt & 1) * 9216u;
        const unsigned uV = uVB + (kt & 1) * 9216u;

        float s[8][4];
#pragma unroll
        for (int nb = 0; nb < 8; ++nb)
#pragma unroll
            for (int c = 0; c < 4; ++c) s[nb][c] = 0.0f;
#pragma unroll
        for (int ks = 0; ks < 4; ++ks) {
            unsigned qf[4];
            ldsm4(qf, uQ + qrow + ks * 32);
#pragma unroll
            for (int jg = 0; jg < 4; ++jg) {
                unsigned kf[4];
                ldsm4(kf, uK + jg * 16 * PITCH + krow + ks * 32);
                mma16816(s[2 * jg],     qf, kf[0], kf[2]);
                mma16816(s[2 * jg + 1], qf, kf[1], kf[3]);
            }
        }

        const bool anymask = (k0 + TK > gi0);
        float* A0 = Aout ? (Aout + ((size_t)bh * LL + gi0) * SS + k0) : (float*)0;
        float* A1 = Aout ? (Aout + ((size_t)bh * LL + gi1) * SS + k0) : (float*)0;

        // per-ks: epilogue for an nb pair, then the PV MMAs for that k-chunk
#pragma unroll
        for (int ks = 0; ks < 4; ++ks) {
            unsigned ah[4];
#pragma unroll
            for (int half = 0; half < 2; ++half) {
                const int nb = 2 * ks + half;
                const int cj = k0 + nb * 8 + 2 * tig;
                float e0 = exp2f(s[nb][0]);
                float e1 = exp2f(s[nb][1]);
                float e2 = exp2f(s[nb][2]);
                float e3 = exp2f(s[nb][3]);
                if (anymask) {
                    if (cj     > gi0) e0 = 0.0f;
                    if (cj + 1 > gi0) e1 = 0.0f;
                    if (cj     > gi1) e2 = 0.0f;
                    if (cj + 1 > gi1) e3 = 0.0f;
                }
                e0 *= inv0; e1 *= inv0; e2 *= inv1; e3 *= inv1;
                if (A0) {
                    __stcs((float2*)(A0 + nb * 8 + 2 * tig), make_float2(e0, e1));
                    __stcs((float2*)(A1 + nb * 8 + 2 * tig), make_float2(e2, e3));
                }
                ah[2 * half]     = pack2h(e0, e1);
                ah[2 * half + 1] = pack2h(e2, e3);
            }
#pragma unroll
            for (int dg = 0; dg < 4; ++dg) {
                unsigned vf[4];
                ldsm4t(vf, uV + ks * 16 * PITCH + krow + dg * 32);
                mma16816(o[2 * dg],     ah, vf[0], vf[1]);
                mma16816(o[2 * dg + 1], ah, vf[2], vf[3]);
            }
        }
    }

    if (Vout) {
        float* O0 = Vout + (((size_t)(b * LL + gi0) * HH + h) * EE);
        float* O1 = Vout + (((size_t)(b * LL + gi1) * HH + h) * EE);
#pragma unroll
        for (int nb = 0; nb < 8; ++nb) {
            *(float2*)(O0 + nb * 8 + 2 * tig) = make_float2(o[nb][0], o[nb][1]);
            *(float2*)(O1 + nb * 8 + 2 * tig) = make_float2(o[nb][2], o[nb][3]);
        }
    }
}

// ---------------------------------------------------------------------------
extern "C" void kernel_launch(void* const* d_in, const int* in_sizes, int n_in,
                              void* d_out, int out_size) {
    const float* Q = (const float*)d_in[0];
    const float* K = (const float*)d_in[1];
    const float* V = (const float*)d_in[2];

    const int V_SIZE = BB * LL * HH * EE;
    const int A_SIZE = (int)((size_t)BB * HH * LL * SS);

    float* out  = (float*)d_out;
    float* Vout = 0;
    float* Aout = 0;
    if (out_size >= V_SIZE + A_SIZE) { Vout = out; Aout = out + V_SIZE; }
    else if (out_size == A_SIZE)     { Aout = out; }
    else                             { Vout = out; }

    const unsigned prep_total = 3u * (NELEM / 4);
    prep<<<(prep_total + 255u) / 256u, 256>>>(Q, K, V);

    const int smem = 55296;
    cudaFuncSetAttribute(attn_tc, cudaFuncAttributeMaxDynamicSharedMemorySize, smem);
    dim3 grid1(LL / TQ, BB * HH);
    attn_tc<<<grid1, 256, smem>>>(Aout, Vout);
}

// round 8
// speedup vs baseline: 2.0442x; 1.1373x over previous
#include <cuda_runtime.h>
#include <cuda_fp16.h>
#include <math.h>

#define BB 2
#define LL 2048
#define SS 2048
#define HH 16
#define EE 64
#define TQ 64
#define TK 64
#define PITCH 144  // smem row pitch: 64 fp16 (128B) + 16B pad

#define NELEM (BB * HH * LL * EE)

__device__ __align__(16) __half gQ[NELEM];
__device__ __align__(16) __half gK[NELEM];
__device__ __align__(16) __half gV[NELEM];

// ---------------- helpers ----------------
__device__ __forceinline__ unsigned smem_u32(const void* p) {
    unsigned a;
    asm("{ .reg .u64 t; cvta.to.shared.u64 t, %1; cvt.u32.u64 %0, t; }"
        : "=r"(a) : "l"(p));
    return a;
}
#define CP16(dst, src) \
    asm volatile("cp.async.cg.shared.global [%0], [%1], 16;" :: "r"(dst), "l"(src))
#define CP_COMMIT() asm volatile("cp.async.commit_group;" ::: "memory")
#define CP_WAIT0()  asm volatile("cp.async.wait_group 0;" ::: "memory")

__device__ __forceinline__ void ldsm4(unsigned r[4], unsigned addr) {
    asm volatile("ldmatrix.sync.aligned.m8n8.x4.shared.b16 {%0,%1,%2,%3}, [%4];"
                 : "=r"(r[0]), "=r"(r[1]), "=r"(r[2]), "=r"(r[3]) : "r"(addr));
}
__device__ __forceinline__ void ldsm4t(unsigned r[4], unsigned addr) {
    asm volatile("ldmatrix.sync.aligned.m8n8.x4.trans.shared.b16 {%0,%1,%2,%3}, [%4];"
                 : "=r"(r[0]), "=r"(r[1]), "=r"(r[2]), "=r"(r[3]) : "r"(addr));
}
__device__ __forceinline__ void mma16816(float* c, const unsigned a[4],
                                         unsigned b0, unsigned b1) {
    asm volatile(
        "mma.sync.aligned.m16n8k16.row.col.f32.f16.f16.f32 "
        "{%0,%1,%2,%3}, {%4,%5,%6,%7}, {%8,%9}, {%0,%1,%2,%3};"
        : "+f"(c[0]), "+f"(c[1]), "+f"(c[2]), "+f"(c[3])
        : "r"(a[0]), "r"(a[1]), "r"(a[2]), "r"(a[3]), "r"(b0), "r"(b1));
}
__device__ __forceinline__ unsigned pack2h(float lo, float hi) {
    __half2 p = __floats2half2_rn(lo, hi);
    return *reinterpret_cast<unsigned*>(&p);
}

// ---------------------------------------------------------------------------
// Prep: fp32 [b,s,h,e] -> fp16 [b,h,s,e]; Q scaled by 0.125*log2(e).
// ---------------------------------------------------------------------------
__global__ __launch_bounds__(256)
void prep(const float* __restrict__ Q, const float* __restrict__ K,
          const float* __restrict__ V) {
    const unsigned per = NELEM / 4;
    unsigned idx = blockIdx.x * 256u + threadIdx.x;
    if (idx >= 3u * per) return;
    const int t = idx / per;
    const unsigned c = idx % per;

    const unsigned e4 = c & 15;
    const unsigned r  = c >> 4;
    const unsigned h  = r & (HH - 1);
    const unsigned bs = r >> 4;
    const unsigned s  = bs & (LL - 1);
    const unsigned b  = bs >> 11;

    const float* src = (t == 0) ? Q : (t == 1) ? K : V;
    float4 v = *(const float4*)(src + (size_t)c * 4);
    if (t == 0) {
        const float sc = 0.18033688011112042f;  // 0.125 * log2(e)
        v.x *= sc; v.y *= sc; v.z *= sc; v.w *= sc;
    }
    __half* oh = (t == 0) ? gQ : (t == 1) ? gK : gV;
    const size_t o = (((size_t)(b * HH + h) * LL + s) * EE) + e4 * 4;
    *(uint2*)(oh + o) = make_uint2(pack2h(v.x, v.y), pack2h(v.z, v.w));
}

// ---------------------------------------------------------------------------
// Fused attention, fp16 MMAs, TQ=64, 4 warps, 4 CTAs/SM for max slot count.
// Sweep 1: exact row sums. Sweep 2: recompute S, write normalized A + O.
// ---------------------------------------------------------------------------
__global__ __launch_bounds__(128, 4)
void attn_tc(float* __restrict__ Aout, float* __restrict__ Vout) {
    extern __shared__ char sm[];
    const unsigned uS  = smem_u32(sm);
    const unsigned uQ  = uS;                 // 64 rows x PITCH = 9216
    const unsigned uKB = uS + 9216;          // 2 bufs x 9216
    const unsigned uVB = uS + 27648;         // 2 bufs x 9216

    const int tid  = threadIdx.x;
    const int lane = tid & 31;
    const int w    = tid >> 5;        // 0..3
    const int g    = lane >> 2;
    const int tig  = lane & 3;

    const int bh = blockIdx.y;
    const int b  = bh / HH, h = bh % HH;
    const int qt = (int)gridDim.x - 1 - (int)blockIdx.x;  // heavy tiles first
    const int q0 = qt * TQ;

    const size_t qbase  = ((size_t)bh * LL + q0) * EE;
    const size_t kvbase = (size_t)bh * LL * EE;
    const int nkt = qt + 1;

    // ---- issue Q tile (512 x 16B) + K tile 0 (512 x 16B) ----
    for (int c = tid; c < 512; c += 128) {
        const int i = c >> 3, ch = c & 7;
        CP16(uQ + i * PITCH + ch * 16, gQ + qbase + (size_t)i * EE + ch * 8);
    }
    for (int c = tid; c < 512; c += 128) {
        const int i = c >> 3, ch = c & 7;
        CP16(uKB + i * PITCH + ch * 16, gK + kvbase + (size_t)i * EE + ch * 8);
    }
    CP_COMMIT();

    const int lr  = (lane & 7) + ((lane >> 3) & 1) * 8;
    const int lco = (lane >> 4) * 8;
    const unsigned qrow = (unsigned)((w * 16 + lr) * PITCH + lco * 2);
    const unsigned krow = (unsigned)(lr * PITCH + lco * 2);

    const int gi0 = q0 + w * 16 + g;
    const int gi1 = gi0 + 8;

    float rsum0 = 0.0f, rsum1 = 0.0f;

    // ================= sweep 1: row sums only =================
    for (int kt = 0; kt < nkt; ++kt) {
        CP_WAIT0();
        __syncthreads();
        if (kt + 1 < nkt) {  // prefetch K[kt+1]
            const unsigned uN = uKB + ((kt + 1) & 1) * 9216u;
            const size_t rb = kvbase + (size_t)(kt + 1) * TK * EE;
            for (int c = tid; c < 512; c += 128) {
                const int i = c >> 3, ch = c & 7;
                CP16(uN + i * PITCH + ch * 16, gK + rb + (size_t)i * EE + ch * 8);
            }
            CP_COMMIT();
        }
        const unsigned uK = uKB + (kt & 1) * 9216u;

        float s[8][4];
#pragma unroll
        for (int nb = 0; nb < 8; ++nb)
#pragma unroll
            for (int c = 0; c < 4; ++c) s[nb][c] = 0.0f;
#pragma unroll
        for (int ks = 0; ks < 4; ++ks) {
            unsigned qf[4];
            ldsm4(qf, uQ + qrow + ks * 32);
#pragma unroll
            for (int jg = 0; jg < 4; ++jg) {
                unsigned kf[4];
                ldsm4(kf, uK + jg * 16 * PITCH + krow + ks * 32);
                mma16816(s[2 * jg],     qf, kf[0], kf[2]);
                mma16816(s[2 * jg + 1], qf, kf[1], kf[3]);
            }
        }
        const int k0 = kt * TK;
        const bool anymask = (k0 + TK > gi0);
#pragma unroll
        for (int nb = 0; nb < 8; ++nb) {
            const int cj = k0 + nb * 8 + 2 * tig;
            float e0 = exp2f(s[nb][0]);
            float e1 = exp2f(s[nb][1]);
            float e2 = exp2f(s[nb][2]);
            float e3 = exp2f(s[nb][3]);
            if (anymask) {
                if (cj     > gi0) e0 = 0.0f;
                if (cj + 1 > gi0) e1 = 0.0f;
                if (cj     > gi1) e2 = 0.0f;
                if (cj + 1 > gi1) e3 = 0.0f;
            }
            rsum0 += e0 + e1;
            rsum1 += e2 + e3;
        }
    }

    rsum0 += __shfl_xor_sync(0xffffffffu, rsum0, 1);
    rsum0 += __shfl_xor_sync(0xffffffffu, rsum0, 2);
    rsum1 += __shfl_xor_sync(0xffffffffu, rsum1, 1);
    rsum1 += __shfl_xor_sync(0xffffffffu, rsum1, 2);
    const float inv0 = 1.0f / rsum0, inv1 = 1.0f / rsum1;

    // ---- issue K0+V0 for sweep 2, overlap zero-fill with loads ----
    __syncthreads();
    for (int c = tid; c < 1024; c += 128) {
        const int arr = c >> 9, i = (c >> 3) & 63, ch = c & 7;
        const __half* gsrc = arr ? gV : gK;
        const unsigned dst = arr ? uVB : uKB;
        CP16(dst + i * PITCH + ch * 16, gsrc + kvbase + (size_t)i * EE + ch * 8);
    }
    CP_COMMIT();

    if (Aout) {  // zero the strictly-upper rectangle of this q-strip
        const int c0 = q0 + TQ;
        const int w4 = (SS - c0) >> 2;
        if (w4 > 0) {
            const float4 z = make_float4(0.f, 0.f, 0.f, 0.f);
            float* Abase = Aout + ((size_t)bh * LL + q0) * SS + c0;
            for (int i = tid; i < TQ * w4; i += 128) {
                const int r = i / w4;
                const int c = i - r * w4;
                __stcs((float4*)(Abase + (size_t)r * SS + 4 * c), z);
            }
        }
    }

    float o[8][4];
#pragma unroll
    for (int nb = 0; nb < 8; ++nb)
#pragma unroll
        for (int c = 0; c < 4; ++c) o[nb][c] = 0.0f;

    // ================= sweep 2: normalized A + O =================
    for (int kt = 0; kt < nkt; ++kt) {
        const int k0 = kt * TK;
        CP_WAIT0();
        __syncthreads();
        if (kt + 1 < nkt) {  // prefetch K/V[kt+1]
            const unsigned nb1 = (kt + 1) & 1;
            const size_t rb = kvbase + (size_t)(kt + 1) * TK * EE;
            for (int c = tid; c < 1024; c += 128) {
                const int arr = c >> 9, i = (c >> 3) & 63, ch = c & 7;
                const __half* gsrc = arr ? gV : gK;
                const unsigned base = (arr ? uVB : uKB) + nb1 * 9216u;
                CP16(base + i * PITCH + ch * 16, gsrc + rb + (size_t)i * EE + ch * 8);
            }
            CP_COMMIT();
        }
        const unsigned uK = uKB + (kt & 1) * 9216u;
        const unsigned uV = uVB + (kt & 1) * 9216u;

        float s[8][4];
#pragma unroll
        for (int nb = 0; nb < 8; ++nb)
#pragma unroll
            for (int c = 0; c < 4; ++c) s[nb][c] = 0.0f;
#pragma unroll
        for (int ks = 0; ks < 4; ++ks) {
            unsigned qf[4];
            ldsm4(qf, uQ + qrow + ks * 32);
#pragma unroll
            for (int jg = 0; jg < 4; ++jg) {
                unsigned kf[4];
                ldsm4(kf, uK + jg * 16 * PITCH + krow + ks * 32);
                mma16816(s[2 * jg],     qf, kf[0], kf[2]);
                mma16816(s[2 * jg + 1], qf, kf[1], kf[3]);
            }
        }

        const bool anymask = (k0 + TK > gi0);
        float* A0 = Aout ? (Aout + ((size_t)bh * LL + gi0) * SS + k0) : (float*)0;
        float* A1 = Aout ? (Aout + ((size_t)bh * LL + gi1) * SS + k0) : (float*)0;

#pragma unroll
        for (int ks = 0; ks < 4; ++ks) {
            unsigned ah[4];
#pragma unroll
            for (int half = 0; half < 2; ++half) {
                const int nb = 2 * ks + half;
                const int cj = k0 + nb * 8 + 2 * tig;
                float e0 = exp2f(s[nb][0]);
                float e1 = exp2f(s[nb][1]);
                float e2 = exp2f(s[nb][2]);
                float e3 = exp2f(s[nb][3]);
                if (anymask) {
                    if (cj     > gi0) e0 = 0.0f;
                    if (cj + 1 > gi0) e1 = 0.0f;
                    if (cj     > gi1) e2 = 0.0f;
                    if (cj + 1 > gi1) e3 = 0.0f;
                }
                e0 *= inv0; e1 *= inv0; e2 *= inv1; e3 *= inv1;
                if (A0) {
                    __stcs((float2*)(A0 + nb * 8 + 2 * tig), make_float2(e0, e1));
                    __stcs((float2*)(A1 + nb * 8 + 2 * tig), make_float2(e2, e3));
                }
                ah[2 * half]     = pack2h(e0, e1);
                ah[2 * half + 1] = pack2h(e2, e3);
            }
#pragma unroll
            for (int dg = 0; dg < 4; ++dg) {
                unsigned vf[4];
                ldsm4t(vf, uV + ks * 16 * PITCH + krow + dg * 32);
                mma16816(o[2 * dg],     ah, vf[0], vf[1]);
                mma16816(o[2 * dg + 1], ah, vf[2], vf[3]);
            }
        }
    }

    if (Vout) {
        float* O0 = Vout + (((size_t)(b * LL + gi0) * HH + h) * EE);
        float* O1 = Vout + (((size_t)(b * LL + gi1) * HH + h) * EE);
#pragma unroll
        for (int nb = 0; nb < 8; ++nb) {
            *(float2*)(O0 + nb * 8 + 2 * tig) = make_float2(o[nb][0], o[nb][1]);
            *(float2*)(O1 + nb * 8 + 2 * tig) = make_float2(o[nb][2], o[nb][3]);
        }
    }
}

// ---------------------------------------------------------------------------
extern "C" void kernel_launch(void* const* d_in, const int* in_sizes, int n_in,
                              void* d_out, int out_size) {
    const float* Q = (const float*)d_in[0];
    const float* K = (const float*)d_in[1];
    const float* V = (const float*)d_in[2];

    const int V_SIZE = BB * LL * HH * EE;
    const int A_SIZE = (int)((size_t)BB * HH * LL * SS);

    float* out  = (float*)d_out;
    float* Vout = 0;
    float* Aout = 0;
    if (out_size >= V_SIZE + A_SIZE) { Vout = out; Aout = out + V_SIZE; }
    else if (out_size == A_SIZE)     { Aout = out; }
    else                             { Vout = out; }

    const unsigned prep_total = 3u * (NELEM / 4);
    prep<<<(prep_total + 255u) / 256u, 256>>>(Q, K, V);

    const int smem = 46080;
    cudaFuncSetAttribute(attn_tc, cudaFuncAttributeMaxDynamicSharedMemorySize, smem);
    dim3 grid1(LL / TQ, BB * HH);
    attn_tc<<<grid1, 128, smem>>>(Aout, Vout);
}